// round 1
// baseline (speedup 1.0000x reference)
#include <cuda_runtime.h>

#define BB   8
#define NN   1024
#define CC   256
#define HID  512
#define FH   256
#define FW   256

// Scratch (allocation-free rule: __device__ globals)
__device__ float g_h0[BB * NN * CC];     //  8 MB
__device__ float g_bufA[BB * NN * HID];  // 16 MB
__device__ float g_bufB[BB * NN * HID];  // 16 MB

// ---------------------------------------------------------------------------
// Bilinear sampling: one block per (b,n) point, one thread per channel.
// Matches jax map_coordinates order=1 mode='constant' (zero outside).
// ---------------------------------------------------------------------------
__global__ void sample_kernel(const float* __restrict__ vert,
                              const float* __restrict__ feat,
                              float* __restrict__ out) {
    int p = blockIdx.x;            // 0 .. BB*NN-1
    int b = p >> 10;
    float y = vert[2 * p + 0];
    float x = vert[2 * p + 1];
    float y0f = floorf(y), x0f = floorf(x);
    int   y0 = (int)y0f,   x0 = (int)x0f;
    float wy1 = y - y0f, wx1 = x - x0f;
    float wy0 = 1.0f - wy1, wx0 = 1.0f - wx1;

    int c = threadIdx.x;           // 0..255
    const float* fb = feat + (size_t)b * FH * FW * CC;

    int   ys[2] = { y0, y0 + 1 };
    int   xs[2] = { x0, x0 + 1 };
    float wy[2] = { wy0, wy1 };
    float wx[2] = { wx0, wx1 };

    float acc = 0.0f;
#pragma unroll
    for (int iy = 0; iy < 2; iy++) {
#pragma unroll
        for (int ix = 0; ix < 2; ix++) {
            int yi = ys[iy], xi = xs[ix];
            if (yi >= 0 && yi < FH && xi >= 0 && xi < FW) {
                acc += fb[((size_t)yi * FW + xi) * CC + c] * (wy[iy] * wx[ix]);
            }
        }
    }
    out[(size_t)p * CC + c] = acc;
}

// ---------------------------------------------------------------------------
// Dilated Conv1D (K=3, SAME zero pad) + bias + ReLU.
// y[n,co] = relu( b[co] + sum_{tap,ci} x[n+(tap-1)*rate, ci] * w[tap,ci,co] )
//
// Tiling: block = 16 consecutive positions (never crosses batch: 16|1024),
// 128 threads, each thread owns 4 co slots {tid, tid+128, tid+256, tid+384}.
// x tiles staged in SMEM (3 taps x 16 pos x 64-ci chunk = 12 KB), weights
// streamed from L2 (co-coalesced). FMA:LDS = 4:1 per inner iteration.
// ---------------------------------------------------------------------------
template <int CIN>
__global__ void __launch_bounds__(128)
conv_kernel(const float* __restrict__ x, const float* __restrict__ w,
            const float* __restrict__ bias, float* __restrict__ y, int rate) {
    constexpr int TN = 16;
    constexpr int CK = 64;
    __shared__ float xs[3][TN][CK];

    int base = blockIdx.x * TN;        // global position index (b*NN + n0)
    int b    = base / NN;
    int n0   = base % NN;
    int tid  = threadIdx.x;

    float acc[TN][4];
#pragma unroll
    for (int p = 0; p < TN; p++)
#pragma unroll
        for (int j = 0; j < 4; j++) acc[p][j] = 0.0f;

    const float* xb = x + (size_t)b * NN * CIN;

    for (int chunk = 0; chunk < CIN / CK; chunk++) {
        __syncthreads();
        // Stage 3 tap-shifted input tiles (float4 loads, zero pad OOB)
        for (int idx = tid; idx < 3 * TN * (CK / 4); idx += 128) {
            int tap = idx / (TN * (CK / 4));
            int r   = idx % (TN * (CK / 4));
            int p   = r / (CK / 4);
            int c4  = r % (CK / 4);
            int n   = n0 + p + (tap - 1) * rate;
            float4 v = make_float4(0.f, 0.f, 0.f, 0.f);
            if (n >= 0 && n < NN) {
                v = *reinterpret_cast<const float4*>(
                        xb + (size_t)n * CIN + chunk * CK + c4 * 4);
            }
            *reinterpret_cast<float4*>(&xs[tap][p][c4 * 4]) = v;
        }
        __syncthreads();

#pragma unroll 4
        for (int ci = 0; ci < CK; ci++) {
            int cig = chunk * CK + ci;
            float wv[3][4];
#pragma unroll
            for (int tap = 0; tap < 3; tap++)
#pragma unroll
                for (int j = 0; j < 4; j++)
                    wv[tap][j] = w[((size_t)tap * CIN + cig) * HID + tid + j * 128];
#pragma unroll
            for (int p = 0; p < TN; p++) {
                float x0v = xs[0][p][ci];
                float x1v = xs[1][p][ci];
                float x2v = xs[2][p][ci];
#pragma unroll
                for (int j = 0; j < 4; j++) {
                    acc[p][j] += x0v * wv[0][j];
                    acc[p][j] += x1v * wv[1][j];
                    acc[p][j] += x2v * wv[2][j];
                }
            }
        }
    }

    float bv[4];
#pragma unroll
    for (int j = 0; j < 4; j++) bv[j] = bias[tid + j * 128];
#pragma unroll
    for (int p = 0; p < TN; p++) {
#pragma unroll
        for (int j = 0; j < 4; j++) {
            float v = acc[p][j] + bv[j];
            v = fmaxf(v, 0.0f);
            y[(size_t)(base + p) * HID + tid + j * 128] = v;
        }
    }
}

// ---------------------------------------------------------------------------
// Offset head (1x1 conv, 512 -> 2, no bias) + vertex add.
// One block (128 threads) per point; shared-memory tree reduction.
// ---------------------------------------------------------------------------
__global__ void head_kernel(const float* __restrict__ h,
                            const float* __restrict__ woff,
                            const float* __restrict__ vert,
                            float* __restrict__ out) {
    int p   = blockIdx.x;
    int tid = threadIdx.x;   // 0..127
    const float* hp = h + (size_t)p * HID;

    float s0 = 0.f, s1 = 0.f;
    for (int ci = tid; ci < HID; ci += 128) {
        float hv = hp[ci];
        s0 += hv * woff[ci * 2 + 0];
        s1 += hv * woff[ci * 2 + 1];
    }
    __shared__ float red0[128];
    __shared__ float red1[128];
    red0[tid] = s0;
    red1[tid] = s1;
    __syncthreads();
#pragma unroll
    for (int off = 64; off > 0; off >>= 1) {
        if (tid < off) {
            red0[tid] += red0[tid + off];
            red1[tid] += red1[tid + off];
        }
        __syncthreads();
    }
    if (tid == 0) {
        out[2 * p + 0] = vert[2 * p + 0] + red0[0];
        out[2 * p + 1] = vert[2 * p + 1] + red1[0];
    }
}

// ---------------------------------------------------------------------------
// Launch
// ---------------------------------------------------------------------------
extern "C" void kernel_launch(void* const* d_in, const int* in_sizes, int n_in,
                              void* d_out, int out_size) {
    const float* vert = (const float*)d_in[0];
    const float* feat = (const float*)d_in[1];
    const float* w[6];
    const float* bpar[6];
    for (int i = 0; i < 6; i++) {
        w[i]    = (const float*)d_in[2 + 2 * i];
        bpar[i] = (const float*)d_in[3 + 2 * i];
    }
    const float* woff = (const float*)d_in[14];
    float* out = (float*)d_out;

    float *h0, *bufA, *bufB;
    cudaGetSymbolAddress((void**)&h0,   g_h0);
    cudaGetSymbolAddress((void**)&bufA, g_bufA);
    cudaGetSymbolAddress((void**)&bufB, g_bufB);

    sample_kernel<<<BB * NN, CC>>>(vert, feat, h0);

    const int conv_blocks = BB * NN / 16;
    conv_kernel<CC><<<conv_blocks, 128>>>(h0,   w[0], bpar[0], bufA, 1);
    conv_kernel<HID><<<conv_blocks, 128>>>(bufA, w[1], bpar[1], bufB, 3);
    conv_kernel<HID><<<conv_blocks, 128>>>(bufB, w[2], bpar[2], bufA, 9);
    conv_kernel<HID><<<conv_blocks, 128>>>(bufA, w[3], bpar[3], bufB, 9);
    conv_kernel<HID><<<conv_blocks, 128>>>(bufB, w[4], bpar[4], bufA, 3);
    conv_kernel<HID><<<conv_blocks, 128>>>(bufA, w[5], bpar[5], bufB, 1);

    head_kernel<<<BB * NN, 128>>>(bufB, woff, vert, out);
}

// round 3
// speedup vs baseline: 6.3760x; 6.3760x over previous
#include <cuda_runtime.h>
#include <cuda_bf16.h>
#include <cstdint>

#define BB   8
#define NN   1024
#define CC   256
#define HID  512
#define FH   256
#define FW   256

// ---------------------------------------------------------------------------
// Scratch (__device__ globals; allocation-free rule)
// ---------------------------------------------------------------------------
__device__ __nv_bfloat16 g_h0[BB * NN * CC];     // sampled features, bf16
__device__ __nv_bfloat16 g_actA[BB * NN * HID];  // activation ping
__device__ __nv_bfloat16 g_actB[BB * NN * HID];  // activation pong
// bf16 weights, original layout [3, CIN, 512]
__device__ __nv_bfloat16 g_wbf[3 * CC * HID + 5 * 3 * HID * HID];

// ---------------------------------------------------------------------------
// PTX helpers (baseline ISA only: cp.async / ldmatrix / mma.sync)
// ---------------------------------------------------------------------------
__device__ __forceinline__ uint32_t s2u(const void* p) {
    return (uint32_t)__cvta_generic_to_shared(p);
}

__device__ __forceinline__ void cp_async16(uint32_t dst, const void* src,
                                           uint32_t src_size) {
    asm volatile("cp.async.cg.shared.global [%0], [%1], 16, %2;"
                 :: "r"(dst), "l"(src), "r"(src_size) : "memory");
}
__device__ __forceinline__ void cp_commit() {
    asm volatile("cp.async.commit_group;" ::: "memory");
}
template <int N>
__device__ __forceinline__ void cp_wait() {
    asm volatile("cp.async.wait_group %0;" :: "n"(N) : "memory");
}

__device__ __forceinline__ void ldsm_x4(uint32_t& r0, uint32_t& r1,
                                        uint32_t& r2, uint32_t& r3, uint32_t a) {
    asm volatile("ldmatrix.sync.aligned.m8n8.x4.shared.b16 {%0,%1,%2,%3}, [%4];"
                 : "=r"(r0), "=r"(r1), "=r"(r2), "=r"(r3) : "r"(a));
}
__device__ __forceinline__ void ldsm_x4t(uint32_t& r0, uint32_t& r1,
                                         uint32_t& r2, uint32_t& r3, uint32_t a) {
    asm volatile("ldmatrix.sync.aligned.m8n8.x4.trans.shared.b16 {%0,%1,%2,%3}, [%4];"
                 : "=r"(r0), "=r"(r1), "=r"(r2), "=r"(r3) : "r"(a));
}

__device__ __forceinline__ void mma_bf16(float& d0, float& d1, float& d2, float& d3,
                                         uint32_t a0, uint32_t a1, uint32_t a2,
                                         uint32_t a3, uint32_t b0, uint32_t b1) {
    asm volatile(
        "mma.sync.aligned.m16n8k16.row.col.f32.bf16.bf16.f32 "
        "{%0,%1,%2,%3}, {%4,%5,%6,%7}, {%8,%9}, {%0,%1,%2,%3};"
        : "+f"(d0), "+f"(d1), "+f"(d2), "+f"(d3)
        : "r"(a0), "r"(a1), "r"(a2), "r"(a3), "r"(b0), "r"(b1));
}

// ---------------------------------------------------------------------------
// Bilinear sampling -> bf16
// ---------------------------------------------------------------------------
__global__ void sample_kernel(const float* __restrict__ vert,
                              const float* __restrict__ feat,
                              __nv_bfloat16* __restrict__ out) {
    int p = blockIdx.x;
    int b = p >> 10;
    float y = vert[2 * p + 0];
    float x = vert[2 * p + 1];
    float y0f = floorf(y), x0f = floorf(x);
    int   y0 = (int)y0f,   x0 = (int)x0f;
    float wy1 = y - y0f, wx1 = x - x0f;
    float wy0 = 1.0f - wy1, wx0 = 1.0f - wx1;

    int c = threadIdx.x;
    const float* fb = feat + (size_t)b * FH * FW * CC;

    int   ys[2] = { y0, y0 + 1 };
    int   xs[2] = { x0, x0 + 1 };
    float wy[2] = { wy0, wy1 };
    float wx[2] = { wx0, wx1 };

    float acc = 0.0f;
#pragma unroll
    for (int iy = 0; iy < 2; iy++)
#pragma unroll
        for (int ix = 0; ix < 2; ix++) {
            int yi = ys[iy], xi = xs[ix];
            if (yi >= 0 && yi < FH && xi >= 0 && xi < FW)
                acc += fb[((size_t)yi * FW + xi) * CC + c] * (wy[iy] * wx[ix]);
        }
    out[(size_t)p * CC + c] = __float2bfloat16(acc);
}

// ---------------------------------------------------------------------------
// f32 -> bf16 weight conversion (layout preserved)
// ---------------------------------------------------------------------------
__global__ void cvt_kernel(const float* __restrict__ w,
                           __nv_bfloat16* __restrict__ o, int n) {
    for (int i = blockIdx.x * blockDim.x + threadIdx.x; i < n;
         i += gridDim.x * blockDim.x)
        o[i] = __float2bfloat16(w[i]);
}

// ---------------------------------------------------------------------------
// Dilated conv layer as mma.sync bf16 GEMM.
//   Y[8192, 512] = relu(bias + sum_tap X_shift[8192, CIN] @ W[tap][CIN, 512])
// Block tile: 128(M) x 64(N), BK=32, double-buffered cp.async staging.
// 256 threads = 8 warps; warp tile 32x32 (2 m-frags x 4 n-frags).
// ---------------------------------------------------------------------------
template <int CIN>
__global__ void __launch_bounds__(256)
conv_mma_kernel(const __nv_bfloat16* __restrict__ X,
                const __nv_bfloat16* __restrict__ W,
                const float* __restrict__ bias,
                __nv_bfloat16* __restrict__ Y, int rate) {
    constexpr int NCH    = 3 * (CIN / 32);   // BK=32 chunks over (tap, k)
    constexpr int APITCH = 80;               // bytes per A row (32 bf16 + pad)
    constexpr int BPITCH = 272;              // bytes per B row (64 bf16-pitch 128B + pad)
    constexpr int ABYTES = 128 * APITCH;     // 10240
    constexpr int BBYTES = 32 * BPITCH;      // 8704
    constexpr int STAGE  = ABYTES + BBYTES;  // 18944

    __shared__ __align__(16) char smem[2 * STAGE];

    const int tid    = threadIdx.x;
    const int wid    = tid >> 5;
    const int lane   = tid & 31;
    const int warp_m = wid >> 1;             // 0..3
    const int warp_n = wid & 1;              // 0..1

    const int nt    = blockIdx.x;            // 0..7   (N tile)
    const int mt    = blockIdx.y;            // 0..63  (M tile)
    const int m0    = mt * 128;
    const int b     = m0 >> 10;
    const int n0    = m0 & (NN - 1);
    const int ncol0 = nt * 64;

    const uint32_t sbase = s2u(smem);

    // staging addresses for this thread
    const int a_row0 = tid >> 1;             // handles rows tid/2 (2 chunks each? no:)
    // A tile: 128 rows x 64B = 512 x 16B chunks; thread handles idx = tid, tid+256
    // B tile: 32 rows x 128B = 256 x 16B chunks; thread handles idx = tid
    const int bi_row = tid >> 3, bi_c8 = tid & 7;

    float acc[2][4][4];
#pragma unroll
    for (int i = 0; i < 2; i++)
#pragma unroll
        for (int j = 0; j < 4; j++)
#pragma unroll
            for (int q = 0; q < 4; q++) acc[i][j][q] = 0.0f;

    auto stage_chunk = [&](int c, int s) {
        const int tap   = c / (CIN / 32);
        const int kc    = c % (CIN / 32);
        const int shift = (tap - 1) * rate;
        const uint32_t abase = sbase + s * STAGE;
        const uint32_t bbase = abase + ABYTES;
#pragma unroll
        for (int rep = 0; rep < 2; rep++) {
            int idx = tid + rep * 256;
            int row = idx >> 2, c4 = idx & 3;
            int n = n0 + row + shift;
            bool valid = (n >= 0) && (n < NN);
            int nc = valid ? n : 0;
            const void* src = X + ((size_t)(b * NN + nc) * CIN + kc * 32 + c4 * 8);
            cp_async16(abase + row * APITCH + c4 * 16, src, valid ? 16u : 0u);
        }
        {
            const void* src = W + ((size_t)(tap * CIN + kc * 32 + bi_row) * HID
                                   + ncol0 + bi_c8 * 8);
            cp_async16(bbase + bi_row * BPITCH + bi_c8 * 16, src, 16u);
        }
        cp_commit();
    };

    stage_chunk(0, 0);

    for (int c = 0; c < NCH; c++) {
        const int s = c & 1;
        if (c + 1 < NCH) stage_chunk(c + 1, (c + 1) & 1);

        if (c + 1 < NCH) cp_wait<1>(); else cp_wait<0>();
        __syncthreads();

        const uint32_t abase = sbase + s * STAGE;
        const uint32_t bbase = abase + ABYTES;

#pragma unroll
        for (int ks = 0; ks < 2; ks++) {
            // A fragments: 2 x m16k16
            uint32_t a[2][4];
#pragma unroll
            for (int mf = 0; mf < 2; mf++) {
                int arow = warp_m * 32 + mf * 16 + (lane & 15);
                int acol = ks * 16 + (lane >> 4) * 8;
                ldsm_x4(a[mf][0], a[mf][1], a[mf][2], a[mf][3],
                        abase + arow * APITCH + acol * 2);
            }
            // B fragments: 2 x (k16 x n16) via x4.trans -> 4 n8-frags
            uint32_t bfr[4][2];
#pragma unroll
            for (int nf2 = 0; nf2 < 2; nf2++) {
                int brow = ks * 16 + (lane & 15);
                int bcol = warp_n * 32 + nf2 * 16 + (lane >> 4) * 8;
                uint32_t r0, r1, r2, r3;
                ldsm_x4t(r0, r1, r2, r3, bbase + brow * BPITCH + bcol * 2);
                bfr[nf2 * 2 + 0][0] = r0; bfr[nf2 * 2 + 0][1] = r1;
                bfr[nf2 * 2 + 1][0] = r2; bfr[nf2 * 2 + 1][1] = r3;
            }
#pragma unroll
            for (int mf = 0; mf < 2; mf++)
#pragma unroll
                for (int nf = 0; nf < 4; nf++)
                    mma_bf16(acc[mf][nf][0], acc[mf][nf][1],
                             acc[mf][nf][2], acc[mf][nf][3],
                             a[mf][0], a[mf][1], a[mf][2], a[mf][3],
                             bfr[nf][0], bfr[nf][1]);
        }
        __syncthreads();
    }

    // ---- epilogue: bias + relu + bf16 stores ----
#pragma unroll
    for (int nf = 0; nf < 4; nf++) {
        int col = ncol0 + warp_n * 32 + nf * 8 + (lane & 3) * 2;
        float b0 = bias[col], b1 = bias[col + 1];
#pragma unroll
        for (int mf = 0; mf < 2; mf++) {
#pragma unroll
            for (int h = 0; h < 2; h++) {
                int row = m0 + warp_m * 32 + mf * 16 + (lane >> 2) + h * 8;
                float v0 = fmaxf(acc[mf][nf][2 * h + 0] + b0, 0.0f);
                float v1 = fmaxf(acc[mf][nf][2 * h + 1] + b1, 0.0f);
                uint32_t pk;
                asm("cvt.rn.bf16x2.f32 %0, %1, %2;" : "=r"(pk) : "f"(v1), "f"(v0));
                *reinterpret_cast<uint32_t*>(Y + ((size_t)row * HID + col)) = pk;
            }
        }
    }
}

// ---------------------------------------------------------------------------
// Offset head (512 -> 2, no bias) + vertex add
// ---------------------------------------------------------------------------
__global__ void head_kernel(const __nv_bfloat16* __restrict__ h,
                            const float* __restrict__ woff,
                            const float* __restrict__ vert,
                            float* __restrict__ out) {
    int p   = blockIdx.x;
    int tid = threadIdx.x;
    const __nv_bfloat16* hp = h + (size_t)p * HID;

    float s0 = 0.f, s1 = 0.f;
    for (int ci = tid; ci < HID; ci += 128) {
        float hv = __bfloat162float(hp[ci]);
        s0 += hv * woff[ci * 2 + 0];
        s1 += hv * woff[ci * 2 + 1];
    }
    __shared__ float red0[128];
    __shared__ float red1[128];
    red0[tid] = s0;
    red1[tid] = s1;
    __syncthreads();
#pragma unroll
    for (int off = 64; off > 0; off >>= 1) {
        if (tid < off) {
            red0[tid] += red0[tid + off];
            red1[tid] += red1[tid + off];
        }
        __syncthreads();
    }
    if (tid == 0) {
        out[2 * p + 0] = vert[2 * p + 0] + red0[0];
        out[2 * p + 1] = vert[2 * p + 1] + red1[0];
    }
}

// ---------------------------------------------------------------------------
// Launch
// ---------------------------------------------------------------------------
extern "C" void kernel_launch(void* const* d_in, const int* in_sizes, int n_in,
                              void* d_out, int out_size) {
    const float* vert = (const float*)d_in[0];
    const float* feat = (const float*)d_in[1];
    const float* w[6];
    const float* bpar[6];
    for (int i = 0; i < 6; i++) {
        w[i]    = (const float*)d_in[2 + 2 * i];
        bpar[i] = (const float*)d_in[3 + 2 * i];
    }
    const float* woff = (const float*)d_in[14];
    float* out = (float*)d_out;

    __nv_bfloat16 *h0, *actA, *actB, *wb;
    cudaGetSymbolAddress((void**)&h0,   g_h0);
    cudaGetSymbolAddress((void**)&actA, g_actA);
    cudaGetSymbolAddress((void**)&actB, g_actB);
    cudaGetSymbolAddress((void**)&wb,   g_wbf);

    // bf16 weight conversion
    size_t wtoff[6];
    wtoff[0] = 0;
    size_t acc = (size_t)3 * CC * HID;
    for (int i = 1; i < 6; i++) { wtoff[i] = acc; acc += (size_t)3 * HID * HID; }
    cvt_kernel<<<256, 256>>>(w[0], wb + wtoff[0], 3 * CC * HID);
    for (int i = 1; i < 6; i++)
        cvt_kernel<<<256, 256>>>(w[i], wb + wtoff[i], 3 * HID * HID);

    sample_kernel<<<BB * NN, CC>>>(vert, feat, h0);

    const int rates[6] = {1, 3, 9, 9, 3, 1};
    dim3 cgrid(HID / 64, BB * NN / 128);     // (8, 64)

    conv_mma_kernel<CC ><<<cgrid, 256>>>(h0,   wb + wtoff[0], bpar[0], actA, rates[0]);
    conv_mma_kernel<HID><<<cgrid, 256>>>(actA, wb + wtoff[1], bpar[1], actB, rates[1]);
    conv_mma_kernel<HID><<<cgrid, 256>>>(actB, wb + wtoff[2], bpar[2], actA, rates[2]);
    conv_mma_kernel<HID><<<cgrid, 256>>>(actA, wb + wtoff[3], bpar[3], actB, rates[3]);
    conv_mma_kernel<HID><<<cgrid, 256>>>(actB, wb + wtoff[4], bpar[4], actA, rates[4]);
    conv_mma_kernel<HID><<<cgrid, 256>>>(actA, wb + wtoff[5], bpar[5], actB, rates[5]);

    head_kernel<<<BB * NN, 128>>>(actB, woff, vert, out);
}